// round 10
// baseline (speedup 1.0000x reference)
#include <cuda_runtime.h>

// ============================================================================
// QuantumLayer (4q, 2 layers, B=524288), Heisenberg picture.
// FOUR samples/thread = two f32x2-packed pairs processed sequentially.
// 128-thread blocks, 8 blocks/SM (64-reg cap) -> single wave (1024 blocks).
// All 4 input LDG.128 issued up front (MLP=4). tanh.approx encoding.
// ============================================================================

using u64 = unsigned long long;

__device__ __forceinline__ u64 mul2(u64 a, u64 b) {
    u64 d; asm("mul.rn.f32x2 %0, %1, %2;" : "=l"(d) : "l"(a), "l"(b)); return d;
}
__device__ __forceinline__ u64 fma2(u64 a, u64 b, u64 c) {
    u64 d; asm("fma.rn.f32x2 %0, %1, %2, %3;" : "=l"(d) : "l"(a), "l"(b), "l"(c)); return d;
}
__device__ __forceinline__ u64 pk(float lo, float hi) {
    u64 d; asm("mov.b64 %0, {%1, %2};" : "=l"(d) : "f"(lo), "f"(hi)); return d;
}
__device__ __forceinline__ float2 upk(u64 a) {
    float2 r; asm("mov.b64 {%0, %1}, %2;" : "=f"(r.x), "=f"(r.y) : "l"(a)); return r;
}
__device__ __forceinline__ float tanha(float x) {
    float y; asm("tanh.approx.f32 %0, %1;" : "=f"(y) : "f"(x)); return y;
}

// Term table: bits0-3 = sin-selection S, bits4-7 = wire-set W, bit8 = sign.
__constant__ unsigned short c_tbl[36] = {
    0x0E0, 0x1E8, 0x0E4, 0x1EC, 0x1E2, 0x1EA, 0x1E6, 0x1EE,   // q0
    0x030, 0x032, 0x031, 0x033,                                 // q1
    0x070, 0x074, 0x172, 0x176, 0x171, 0x175, 0x173, 0x177,     // q2
    0x0F0, 0x0F8, 0x1F4, 0x1FC, 0x0F2, 0x1FA, 0x0F6, 0x1FE,     // q3
    0x0F1, 0x0F9, 0x1F5, 0x1FD, 0x0F3, 0x0FB, 0x0F7, 0x0FF
};

struct SmemConsts {
    u64   cph2[4], sph2[4];
    float w0y[4];
    float cth[4], sth[4];
    u64   coef[36];
};

// Encoding + 36-term factored Pauli sum for one packed pair of samples.
__device__ __forceinline__ void eval_pair(
    const float4& xva, const float4& xvb, const SmemConsts& S,
    u64& a0, u64& a1, u64& a2, u64& a3)
{
    const float PI = 3.14159265358979f;
    float xa[4] = {xva.x, xva.y, xva.z, xva.w};
    float xb[4] = {xvb.x, xvb.y, xvb.z, xvb.w};

    u64 X[4], Y[4], Z[4];
    #pragma unroll
    for (int q = 0; q < 4; q++) {
        float w0 = S.w0y[q];
        float aA = fmaf(tanha(xa[q]), PI, w0);
        float aB = fmaf(tanha(xb[q]), PI, w0);
        float sA, cA; __sincosf(aA, &sA, &cA);
        float sB, cB; __sincosf(aB, &sB, &cB);
        u64 sa = pk(sA, sB);
        Z[q] = pk(cA, cB);
        X[q] = mul2(sa, S.cph2[q]);
        Y[q] = mul2(sa, S.sph2[q]);
    }

    u64 y01 = mul2(Y[0], Y[1]), x01 = mul2(X[0], X[1]);
    u64 x12 = mul2(X[1], X[2]), y12 = mul2(Y[1], Y[2]);
    u64 z01 = mul2(Z[0], Z[1]), z12 = mul2(Z[1], Z[2]);
    u64 x02 = mul2(X[0], X[2]), z02 = mul2(Z[0], Z[2]);
    u64 yz01 = mul2(Y[0], Z[1]);
    u64 x01z2 = mul2(x01, Z[2]);
    u64 yzy   = mul2(yz01, Y[2]);
    u64 yx2   = mul2(y01, X[2]);

    const u64* C = S.coef;

    u64 g0z = fma2(C[4], x12, mul2(C[0], z01));
    u64 g0y = fma2(C[6], mul2(Y[1], z02), mul2(C[2], Y[2]));
    u64 g0x = fma2(C[5], yzy, mul2(C[1], x01z2));
    u64 g0c = fma2(C[3], yx2, mul2(C[7], X[0]));
    a0 = fma2(g0z, Z[3], fma2(g0y, Y[3], fma2(g0x, X[3], g0c)));

    u64 g1z = fma2(C[9], y12, mul2(C[8], z02));
    u64 g1c = fma2(C[11], x02, mul2(C[10], y01));
    a1 = fma2(g1z, Z[3], g1c);

    u64 g2z = fma2(C[14], mul2(Z[0], x12), mul2(C[12], Z[1]));
    u64 g2y = fma2(C[15], mul2(Y[1], Z[2]), mul2(C[13], mul2(Z[0], Y[2])));
    u64 g2x = fma2(C[17], yx2, mul2(C[19], X[0]));
    u64 g2c = fma2(C[16], x01z2, mul2(C[18], yzy));
    a2 = fma2(g2z, Z[3], fma2(g2y, Y[3], fma2(g2x, X[3], g2c)));

    u64 g3z = fma2(C[23], mul2(mul2(Y[0], X[1]), Y[2]),
              fma2(C[27], mul2(X[0], z12),
              fma2(C[28], y01, mul2(C[32], x02))));
    u64 g3y = fma2(C[21], mul2(X[0], Y[1]),
              fma2(C[25], mul2(Y[0], X[2]),
              fma2(C[30], mul2(x01, Y[2]), mul2(C[34], mul2(yz01, Z[2])))));
    u64 g3x = fma2(C[22], mul2(Z[1], X[2]),
              fma2(C[26], mul2(Z[0], X[1]),
              fma2(C[33], mul2(Z[0], y12), mul2(C[29], Z[2]))));
    u64 g3c = fma2(C[20], z02,
              fma2(C[24], y12,
              fma2(C[31], mul2(z01, X[2]), mul2(C[35], X[1]))));
    a3 = fma2(g3z, Z[3], fma2(g3y, Y[3], fma2(g3x, X[3], g3c)));
}

__global__ __launch_bounds__(128, 8)
void circuit_kernel(const float* __restrict__ x, const float* __restrict__ w,
                    float* __restrict__ out, int NQUAD) {
    __shared__ SmemConsts S;

    const int t = threadIdx.x;
    if (t < 4) {
        float sp, cp; __sincosf(w[2 * t + 1], &sp, &cp);
        S.sph2[t] = pk(sp, sp); S.cph2[t] = pk(cp, cp);
        S.w0y[t] = w[2 * t];
    } else if (t < 8) {
        int j = t - 4;
        float st, ct; __sincosf(w[8 + 2 * j], &st, &ct);
        S.sth[j] = st; S.cth[j] = ct;
    }
    __syncthreads();
    if (t < 36) {
        unsigned e = c_tbl[t];
        float v = 1.0f;
        #pragma unroll
        for (int j = 0; j < 4; j++)
            if ((e >> (4 + j)) & 1) v *= ((e >> j) & 1) ? S.sth[j] : S.cth[j];
        if (e & 0x100) v = -v;
        S.coef[t] = pk(v, v);
    }
    __syncthreads();

    int tid = blockIdx.x * blockDim.x + t;
    if (tid >= NQUAD) return;

    // Issue all four sample loads up front (MLP = 4).
    const float4* x4 = reinterpret_cast<const float4*>(x);
    float4 x0 = x4[4 * tid];
    float4 x1 = x4[4 * tid + 1];
    float4 x2 = x4[4 * tid + 2];
    float4 x3 = x4[4 * tid + 3];

    float4* o4 = reinterpret_cast<float4*>(out);

    // ---- pair 0 (samples 0,1) ----
    {
        u64 a0, a1, a2, a3;
        eval_pair(x0, x1, S, a0, a1, a2, a3);
        float2 f0 = upk(a0), f1 = upk(a1), f2 = upk(a2), f3 = upk(a3);
        float4 oa; oa.x = f0.x; oa.y = f1.x; oa.z = f2.x; oa.w = f3.x;
        float4 ob; ob.x = f0.y; ob.y = f1.y; ob.z = f2.y; ob.w = f3.y;
        o4[4 * tid]     = oa;
        o4[4 * tid + 1] = ob;
    }
    // ---- pair 1 (samples 2,3) ----
    {
        u64 a0, a1, a2, a3;
        eval_pair(x2, x3, S, a0, a1, a2, a3);
        float2 f0 = upk(a0), f1 = upk(a1), f2 = upk(a2), f3 = upk(a3);
        float4 oa; oa.x = f0.x; oa.y = f1.x; oa.z = f2.x; oa.w = f3.x;
        float4 ob; ob.x = f0.y; ob.y = f1.y; ob.z = f2.y; ob.w = f3.y;
        o4[4 * tid + 2] = oa;
        o4[4 * tid + 3] = ob;
    }
}

extern "C" void kernel_launch(void* const* d_in, const int* in_sizes, int n_in,
                              void* d_out, int out_size) {
    const float* x = (const float*)d_in[0];     // [B, 4]
    const float* w = (const float*)d_in[1];     // [2, 4, 2]
    float* out = (float*)d_out;                 // [B, 4]
    int B = in_sizes[0] / 4;
    int nquad = B / 4;                           // B divisible by 4

    int threads = 128;
    int blocks = (nquad + threads - 1) / threads;
    circuit_kernel<<<blocks, threads>>>(x, w, out, nquad);
}

// round 11
// speedup vs baseline: 1.9928x; 1.9928x over previous
#include <cuda_runtime.h>

// ============================================================================
// QuantumLayer (4q, 2 layers, B=524288), Heisenberg picture.
// ONE sample per thread (max thread-level parallelism to hide latency),
// tanh.approx encoding, wire-3-factored 36-term Pauli sum (short chains),
// single __syncthreads block prep.
// ============================================================================

__device__ __forceinline__ float tanha(float x) {
    float y; asm("tanh.approx.f32 %0, %1;" : "=f"(y) : "f"(x)); return y;
}

// Term table: bits0-3 = sin-selection S, bits4-7 = wire-set W, bit8 = sign.
__constant__ unsigned short c_tbl[36] = {
    0x0E0, 0x1E8, 0x0E4, 0x1EC, 0x1E2, 0x1EA, 0x1E6, 0x1EE,   // q0
    0x030, 0x032, 0x031, 0x033,                                 // q1
    0x070, 0x074, 0x172, 0x176, 0x171, 0x175, 0x173, 0x177,     // q2
    0x0F0, 0x0F8, 0x1F4, 0x1FC, 0x0F2, 0x1FA, 0x0F6, 0x1FE,     // q3
    0x0F1, 0x0F9, 0x1F5, 0x1FD, 0x0F3, 0x0FB, 0x0F7, 0x0FF
};

__global__ __launch_bounds__(256)
void circuit_kernel(const float* __restrict__ x, const float* __restrict__ w,
                    float* __restrict__ out, int B) {
    __shared__ float s_cph[4], s_sph[4], s_w0y[4];
    __shared__ float s_coef[36];

    const int t = threadIdx.x;
    // Single-barrier prep: coef threads compute layer-1 trig redundantly.
    if (t < 4) {
        float sp, cp; __sincosf(w[2 * t + 1], &sp, &cp);
        s_sph[t] = sp; s_cph[t] = cp;
        s_w0y[t] = w[2 * t];
    }
    if (t < 36) {
        unsigned e = c_tbl[t];
        float v = 1.0f;
        #pragma unroll
        for (int j = 0; j < 4; j++) {
            if ((e >> (4 + j)) & 1) {
                float st, ct; __sincosf(w[8 + 2 * j], &st, &ct);
                v *= ((e >> j) & 1) ? st : ct;
            }
        }
        s_coef[t] = (e & 0x100) ? -v : v;
    }
    __syncthreads();

    int b = blockIdx.x * blockDim.x + t;
    if (b >= B) return;

    float4 xv = reinterpret_cast<const float4*>(x)[b];
    float xs[4] = {xv.x, xv.y, xv.z, xv.w};

    // Bloch vectors: a = pi*tanh(x) + w0y.
    const float PI = 3.14159265358979f;
    float X[4], Y[4], Z[4];
    #pragma unroll
    for (int q = 0; q < 4; q++) {
        float a = fmaf(tanha(xs[q]), PI, s_w0y[q]);
        float sa, ca; __sincosf(a, &sa, &ca);
        X[q] = sa * s_cph[q];
        Y[q] = sa * s_sph[q];
        Z[q] = ca;
    }

    // Shared sub-products.
    float y01 = Y[0]*Y[1], x01 = X[0]*X[1];
    float x12 = X[1]*X[2], y12 = Y[1]*Y[2];
    float z01 = Z[0]*Z[1], z12 = Z[1]*Z[2];
    float x02 = X[0]*X[2], z02 = Z[0]*Z[2];
    float yz01 = Y[0]*Z[1];
    float x01z2 = x01 * Z[2];
    float yzy   = yz01 * Y[2];      // y0 z1 y2
    float yx2   = y01 * X[2];       // y0 y1 x2

    const float* C = s_coef;

    // ---- <Z_0>: factored by wire-3 operator ----
    float g0z = fmaf(C[4], x12, C[0] * z01);
    float g0y = fmaf(C[6], Y[1] * z02, C[2] * Y[2]);
    float g0x = fmaf(C[5], yzy, C[1] * x01z2);
    float g0c = fmaf(C[3], yx2, C[7] * X[0]);
    float a0 = fmaf(g0z, Z[3], fmaf(g0y, Y[3], fmaf(g0x, X[3], g0c)));

    // ---- <Z_1> ----
    float g1z = fmaf(C[9], y12, C[8] * z02);
    float g1c = fmaf(C[11], x02, C[10] * y01);
    float a1 = fmaf(g1z, Z[3], g1c);

    // ---- <Z_2> ----
    float g2z = fmaf(C[14], Z[0] * x12, C[12] * Z[1]);
    float g2y = fmaf(C[15], Y[1] * Z[2], C[13] * (Z[0] * Y[2]));
    float g2x = fmaf(C[17], yx2, C[19] * X[0]);
    float g2c = fmaf(C[16], x01z2, C[18] * yzy);
    float a2 = fmaf(g2z, Z[3], fmaf(g2y, Y[3], fmaf(g2x, X[3], g2c)));

    // ---- <Z_3> ----
    float g3z = fmaf(C[23], (Y[0] * X[1]) * Y[2],
                fmaf(C[27], X[0] * z12,
                fmaf(C[28], y01, C[32] * x02)));
    float g3y = fmaf(C[21], X[0] * Y[1],
                fmaf(C[25], Y[0] * X[2],
                fmaf(C[30], x01 * Y[2], C[34] * (yz01 * Z[2]))));
    float g3x = fmaf(C[22], Z[1] * X[2],
                fmaf(C[26], Z[0] * X[1],
                fmaf(C[33], Z[0] * y12, C[29] * Z[2])));
    float g3c = fmaf(C[20], z02,
                fmaf(C[24], y12,
                fmaf(C[31], z01 * X[2], C[35] * X[1])));
    float a3 = fmaf(g3z, Z[3], fmaf(g3y, Y[3], fmaf(g3x, X[3], g3c)));

    float4 o; o.x = a0; o.y = a1; o.z = a2; o.w = a3;
    reinterpret_cast<float4*>(out)[b] = o;
}

extern "C" void kernel_launch(void* const* d_in, const int* in_sizes, int n_in,
                              void* d_out, int out_size) {
    const float* x = (const float*)d_in[0];     // [B, 4]
    const float* w = (const float*)d_in[1];     // [2, 4, 2]
    float* out = (float*)d_out;                 // [B, 4]
    int B = in_sizes[0] / 4;

    int threads = 256;
    int blocks = (B + threads - 1) / threads;
    circuit_kernel<<<blocks, threads>>>(x, w, out, B);
}

// round 13
// speedup vs baseline: 2.0441x; 1.0257x over previous
#include <cuda_runtime.h>

// ============================================================================
// QuantumLayer (4q, 2 layers, B=524288), Heisenberg picture.
// 2 samples/thread (i and i+B/2, both coalesced), BOTH LDG.128 up front,
// computed sequentially -> second load's DRAM latency hidden behind first
// sample's compute. Shared constants packed as float4 (LDS.128).
// tanh.approx encoding, wire-3-factored 36-term Pauli sum.
// ============================================================================

__device__ __forceinline__ float tanha(float x) {
    float y; asm("tanh.approx.f32 %0, %1;" : "=f"(y) : "f"(x)); return y;
}

// Term table: bits0-3 = sin-selection S, bits4-7 = wire-set W, bit8 = sign.
__constant__ unsigned short c_tbl[36] = {
    0x0E0, 0x1E8, 0x0E4, 0x1EC, 0x1E2, 0x1EA, 0x1E6, 0x1EE,   // q0
    0x030, 0x032, 0x031, 0x033,                                 // q1
    0x070, 0x074, 0x172, 0x176, 0x171, 0x175, 0x173, 0x177,     // q2
    0x0F0, 0x0F8, 0x1F4, 0x1FC, 0x0F2, 0x1FA, 0x0F6, 0x1FE,     // q3
    0x0F1, 0x0F9, 0x1F5, 0x1FD, 0x0F3, 0x0FB, 0x0F7, 0x0FF
};

// s_enc[q] = {cos(phi_q), sin(phi_q), w0y_q, 0}; s_cf[0..8] = coefs 0..35.
__device__ __forceinline__ float4 eval_sample(const float4 xv,
                                              const float4* s_enc,
                                              const float4* s_cf) {
    const float PI = 3.14159265358979f;
    float xs[4] = {xv.x, xv.y, xv.z, xv.w};

    float X[4], Y[4], Z[4];
    #pragma unroll
    for (int q = 0; q < 4; q++) {
        float4 e = s_enc[q];
        float a = fmaf(tanha(xs[q]), PI, e.z);
        float sa, ca; __sincosf(a, &sa, &ca);
        X[q] = sa * e.x;
        Y[q] = sa * e.y;
        Z[q] = ca;
    }

    float y01 = Y[0]*Y[1], x01 = X[0]*X[1];
    float x12 = X[1]*X[2], y12 = Y[1]*Y[2];
    float z01 = Z[0]*Z[1], z12 = Z[1]*Z[2];
    float x02 = X[0]*X[2], z02 = Z[0]*Z[2];
    float yz01 = Y[0]*Z[1];
    float x01z2 = x01 * Z[2];
    float yzy   = yz01 * Y[2];
    float yx2   = y01 * X[2];

    // ---- <Z_0>: C0..C7 ----
    float4 cA = s_cf[0], cB = s_cf[1];
    float g0z = fmaf(cB.x, x12, cA.x * z01);
    float g0y = fmaf(cB.z, Y[1] * z02, cA.z * Y[2]);
    float g0x = fmaf(cB.y, yzy, cA.y * x01z2);
    float g0c = fmaf(cA.w, yx2, cB.w * X[0]);
    float a0 = fmaf(g0z, Z[3], fmaf(g0y, Y[3], fmaf(g0x, X[3], g0c)));

    // ---- <Z_1>: C8..C11 ----
    float4 cC = s_cf[2];
    float g1z = fmaf(cC.y, y12, cC.x * z02);
    float g1c = fmaf(cC.w, x02, cC.z * y01);
    float a1 = fmaf(g1z, Z[3], g1c);

    // ---- <Z_2>: C12..C19 ----
    float4 cD = s_cf[3], cE = s_cf[4];
    float g2z = fmaf(cD.z, Z[0] * x12, cD.x * Z[1]);
    float g2y = fmaf(cD.w, Y[1] * Z[2], cD.y * (Z[0] * Y[2]));
    float g2x = fmaf(cE.y, yx2, cE.w * X[0]);
    float g2c = fmaf(cE.x, x01z2, cE.z * yzy);
    float a2 = fmaf(g2z, Z[3], fmaf(g2y, Y[3], fmaf(g2x, X[3], g2c)));

    // ---- <Z_3>: C20..C35 ----
    float4 cF = s_cf[5], cG = s_cf[6], cH = s_cf[7], cI = s_cf[8];
    float g3z = fmaf(cF.w, (Y[0] * X[1]) * Y[2],
                fmaf(cG.w, X[0] * z12,
                fmaf(cH.x, y01, cI.x * x02)));
    float g3y = fmaf(cF.y, X[0] * Y[1],
                fmaf(cG.y, Y[0] * X[2],
                fmaf(cH.z, x01 * Y[2], cI.z * (yz01 * Z[2]))));
    float g3x = fmaf(cF.z, Z[1] * X[2],
                fmaf(cG.z, Z[0] * X[1],
                fmaf(cI.y, Z[0] * y12, cH.y * Z[2])));
    float g3c = fmaf(cF.x, z02,
                fmaf(cG.x, y12,
                fmaf(cH.w, z01 * X[2], cI.w * X[1])));
    float a3 = fmaf(g3z, Z[3], fmaf(g3y, Y[3], fmaf(g3x, X[3], g3c)));

    float4 o; o.x = a0; o.y = a1; o.z = a2; o.w = a3;
    return o;
}

__global__ __launch_bounds__(256)
void circuit_kernel(const float* __restrict__ x, const float* __restrict__ w,
                    float* __restrict__ out, int NPAIR) {
    __shared__ float4 s_enc[4];
    __shared__ float4 s_cf[9];

    const int t = threadIdx.x;
    if (t < 4) {
        float sp, cp; __sincosf(w[2 * t + 1], &sp, &cp);
        s_enc[t] = make_float4(cp, sp, w[2 * t], 0.0f);
    }
    if (t < 36) {
        unsigned e = c_tbl[t];
        float v = 1.0f;
        #pragma unroll
        for (int j = 0; j < 4; j++) {
            if ((e >> (4 + j)) & 1) {
                float st, ct; __sincosf(w[8 + 2 * j], &st, &ct);
                v *= ((e >> j) & 1) ? st : ct;
            }
        }
        reinterpret_cast<float*>(s_cf)[t] = (e & 0x100) ? -v : v;
    }
    __syncthreads();

    int i0 = blockIdx.x * blockDim.x + t;
    if (i0 >= NPAIR) return;
    int i1 = i0 + NPAIR;

    // Both loads issued back-to-back up front (MLP=2); i1's DRAM latency
    // hides behind sample-0 compute.
    const float4* x4 = reinterpret_cast<const float4*>(x);
    float4 xv0 = x4[i0];
    float4 xv1 = x4[i1];

    float4* o4 = reinterpret_cast<float4*>(out);
    o4[i0] = eval_sample(xv0, s_enc, s_cf);
    o4[i1] = eval_sample(xv1, s_enc, s_cf);
}

extern "C" void kernel_launch(void* const* d_in, const int* in_sizes, int n_in,
                              void* d_out, int out_size) {
    const float* x = (const float*)d_in[0];     // [B, 4]
    const float* w = (const float*)d_in[1];     // [2, 4, 2]
    float* out = (float*)d_out;                 // [B, 4]
    int B = in_sizes[0] / 4;
    int npair = B / 2;

    int threads = 256;
    int blocks = (npair + threads - 1) / threads;
    circuit_kernel<<<blocks, threads>>>(x, w, out, npair);
}